// round 10
// baseline (speedup 1.0000x reference)
#include <cuda_runtime.h>
#include <cuda_bf16.h>
#include <math.h>

#define BDIM   64
#define LDIM   1024
#define INDIM  512
#define HDIM   512
#define G3     1536
#define NCTA_DIR 64
#define HS     8

typedef unsigned long long u64;

// ---------- static device scratch (no allocations) ----------
// gx layout: [dir][t][gate][unit][batch]  (batch innermost, coalesced for scan)
__device__ float g_gx[(size_t)2 * BDIM * LDIM * G3];
__device__ __nv_bfloat16 g_xb[(size_t)BDIM * LDIM * 1536];    // A' rows m' = l*64+b
__device__ __nv_bfloat16 g_wb[(size_t)2 * 1536 * 1536];       // B' = [hi|lo|hi] per dir
__device__ unsigned g_hx[2 * 2 * BDIM * HDIM];                // [dir][buf][b][k] bf16 hi|lo
__device__ unsigned g_ticket2[2][32];                         // per-dir tickets, padded

// =====================================================================
// helpers
// =====================================================================
__device__ __forceinline__ unsigned pack_bf16x2(float a, float b)
{
    unsigned lo = (unsigned)__bfloat16_as_ushort(__float2bfloat16(a));
    unsigned hi = (unsigned)__bfloat16_as_ushort(__float2bfloat16(b));
    return lo | (hi << 16);
}
__device__ __forceinline__ float bf16_hi(float v)
{
    return __bfloat162float(__float2bfloat16(v));
}
__device__ __forceinline__ unsigned prmt(unsigned a, unsigned b, unsigned sel)
{
    unsigned d;
    asm("prmt.b32 %0, %1, %2, %3;" : "=r"(d) : "r"(a), "r"(b), "r"(sel));
    return d;
}

__global__ void convx_kernel(const float* __restrict__ X)
{
    const size_t i = (size_t)blockIdx.x * 256 + threadIdx.x;   // < 8388608
    float4 v = ((const float4*)X)[i];
    const size_t m  = i >> 7;          // b*1024 + l
    const int    kq = (int)(i & 127);
    const int    b  = (int)(m >> 10);
    const int    l  = (int)(m & 1023);
    const size_t mp = (size_t)l * 64 + b;     // permuted row
    uint2 h, lo;
    h.x  = pack_bf16x2(v.x, v.y);
    h.y  = pack_bf16x2(v.z, v.w);
    lo.x = pack_bf16x2(v.x - bf16_hi(v.x), v.y - bf16_hi(v.y));
    lo.y = pack_bf16x2(v.z - bf16_hi(v.z), v.w - bf16_hi(v.w));
    __nv_bfloat16* d = g_xb + mp * 1536 + kq * 4;
    *(uint2*)(d)        = h;
    *(uint2*)(d + 512)  = h;
    *(uint2*)(d + 1024) = lo;
}

__global__ void convw_kernel(const float* __restrict__ Wlr, const float* __restrict__ Wrl)
{
    const int i   = blockIdx.x * 256 + threadIdx.x;            // < 393216
    const int dir = i / 196608;
    const int rem = i - dir * 196608;
    const int n   = rem >> 7;
    const int kq  = rem & 127;
    const float* W = dir ? Wrl : Wlr;
    float4 v = ((const float4*)W)[rem];
    uint2 h, lo;
    h.x  = pack_bf16x2(v.x, v.y);
    h.y  = pack_bf16x2(v.z, v.w);
    lo.x = pack_bf16x2(v.x - bf16_hi(v.x), v.y - bf16_hi(v.y));
    lo.y = pack_bf16x2(v.z - bf16_hi(v.z), v.w - bf16_hi(v.w));
    __nv_bfloat16* d = g_wb + (size_t)dir * 1536 * 1536 + (size_t)n * 1536 + kq * 4;
    *(uint2*)(d)        = h;
    *(uint2*)(d + 512)  = lo;
    *(uint2*)(d + 1024) = h;
}

// =====================================================================
// mma primitives
// =====================================================================
__device__ __forceinline__ void ldsm4(unsigned& r0, unsigned& r1, unsigned& r2, unsigned& r3,
                                      const void* p)
{
    unsigned a = (unsigned)__cvta_generic_to_shared(p);
    asm volatile("ldmatrix.sync.aligned.m8n8.x4.shared.b16 {%0,%1,%2,%3}, [%4];"
                 : "=r"(r0), "=r"(r1), "=r"(r2), "=r"(r3) : "r"(a));
}
__device__ __forceinline__ void mma16816(float* c, const unsigned* a, unsigned b0, unsigned b1)
{
    asm volatile("mma.sync.aligned.m16n8k16.row.col.f32.bf16.bf16.f32 "
                 "{%0,%1,%2,%3}, {%4,%5,%6,%7}, {%8,%9}, {%0,%1,%2,%3};"
                 : "+f"(c[0]), "+f"(c[1]), "+f"(c[2]), "+f"(c[3])
                 : "r"(a[0]), "r"(a[1]), "r"(a[2]), "r"(a[3]), "r"(b0), "r"(b1));
}

// =====================================================================
// Input-projection GEMM. Rows are m' = l*64+b. Output written to the
// transposed gx layout [t][g][u][b].
// =====================================================================
__global__ void __launch_bounds__(256, 1)
hgemm_kernel(const float* __restrict__ blr, const float* __restrict__ brl)
{
    __shared__ __nv_bfloat16 As[2][128][40];
    __shared__ __nv_bfloat16 Bs[2][128][40];

    const int tid  = threadIdx.x;
    const int lane = tid & 31;
    const int wid  = tid >> 5;
    const int dir  = blockIdx.z;
    const int m0   = blockIdx.y * 128;
    const int n0   = blockIdx.x * 128;
    const int wm   = wid >> 1;
    const int wn   = wid & 1;

    const int row0 = tid >> 2;
    const int cc   = tid & 3;

    const __nv_bfloat16* ga0 = g_xb + (size_t)(m0 + row0) * 1536 + cc * 8;
    const __nv_bfloat16* gb0 = g_wb + (size_t)dir * 1536 * 1536
                                    + (size_t)(n0 + row0) * 1536 + cc * 8;

    uint4 av0 = *(const uint4*)ga0;
    uint4 av1 = *(const uint4*)(ga0 + (size_t)64 * 1536);
    uint4 bv0 = *(const uint4*)gb0;
    uint4 bv1 = *(const uint4*)(gb0 + (size_t)64 * 1536);
    *(uint4*)&As[0][row0][cc * 8]      = av0;
    *(uint4*)&As[0][row0 + 64][cc * 8] = av1;
    *(uint4*)&Bs[0][row0][cc * 8]      = bv0;
    *(uint4*)&Bs[0][row0 + 64][cc * 8] = bv1;
    __syncthreads();

    float acc[2][8][4];
    #pragma unroll
    for (int mt = 0; mt < 2; ++mt)
        #pragma unroll
        for (int nt = 0; nt < 8; ++nt)
            #pragma unroll
            for (int q = 0; q < 4; ++q) acc[mt][nt][q] = 0.0f;

    #pragma unroll 1
    for (int kt = 0; kt < 48; ++kt) {
        const int buf = kt & 1;
        if (kt < 47) {
            const int off = (kt + 1) * 32;
            av0 = *(const uint4*)(ga0 + off);
            av1 = *(const uint4*)(ga0 + (size_t)64 * 1536 + off);
            bv0 = *(const uint4*)(gb0 + off);
            bv1 = *(const uint4*)(gb0 + (size_t)64 * 1536 + off);
        }
        #pragma unroll
        for (int ks = 0; ks < 2; ++ks) {
            unsigned af[2][4], bfr[4][4];
            #pragma unroll
            for (int mt = 0; mt < 2; ++mt)
                ldsm4(af[mt][0], af[mt][1], af[mt][2], af[mt][3],
                      &As[buf][wm * 32 + mt * 16 + (lane & 15)][ks * 16 + (lane >> 4) * 8]);
            #pragma unroll
            for (int nt2 = 0; nt2 < 4; ++nt2)
                ldsm4(bfr[nt2][0], bfr[nt2][1], bfr[nt2][2], bfr[nt2][3],
                      &Bs[buf][wn * 64 + nt2 * 16 + (lane & 15)][ks * 16 + (lane >> 4) * 8]);
            #pragma unroll
            for (int mt = 0; mt < 2; ++mt)
                #pragma unroll
                for (int nt = 0; nt < 8; ++nt)
                    mma16816(acc[mt][nt], af[mt],
                             bfr[nt >> 1][nt & 1], bfr[nt >> 1][2 + (nt & 1)]);
        }
        if (kt < 47) {
            const int nb = buf ^ 1;
            *(uint4*)&As[nb][row0][cc * 8]      = av0;
            *(uint4*)&As[nb][row0 + 64][cc * 8] = av1;
            *(uint4*)&Bs[nb][row0][cc * 8]      = bv0;
            *(uint4*)&Bs[nb][row0 + 64][cc * 8] = bv1;
        }
        __syncthreads();
    }

    const float* bia = dir ? brl : blr;
    float* C = g_gx + (size_t)dir * ((size_t)BDIM * LDIM * G3);
    #pragma unroll
    for (int mt = 0; mt < 2; ++mt) {
        #pragma unroll
        for (int nt = 0; nt < 8; ++nt) {
            const int nc = n0 + wn * 64 + nt * 8 + (lane & 3) * 2;
            const int g  = nc >> 9, j = nc & 511;
            const float bx = bia[nc], by = bia[nc + 1];
            #pragma unroll
            for (int q = 0; q < 2; ++q) {
                const int rl = wm * 32 + mt * 16 + (lane >> 2) + q * 8;
                const int b  = rl & 63;
                const int l  = (m0 + rl) >> 6;
                float* p = C + ((size_t)(l * 3 + g) * 512 + j) * 64 + b;
                p[0]  = acc[mt][nt][q * 2 + 0] + bx;
                p[64] = acc[mt][nt][q * 2 + 1] + by;
            }
        }
    }
}

// =====================================================================
// Tensor-core recurrent scan (structure as R8). New: coalesced gx reads,
// per-direction release/acquire ticket barrier with nanosleep backoff.
// =====================================================================
#define APITCH  1040
#define OFF_AHI 0
#define OFF_ALO 66560
#define OFF_BHI 133120
#define OFF_BLO 166400
#define OFF_RED 199680
#define OFF_OUTS 212992
#define OFF_OHX  215040
#define SM_BYTES 217088

__device__ __forceinline__ void grid_barrier(int dir)
{
    __syncthreads();
    if (threadIdx.x == 0) {
        unsigned* t = &g_ticket2[dir][0];
        unsigned v;
        asm volatile("atom.release.gpu.global.add.u32 %0, [%1], %2;"
                     : "=r"(v) : "l"(t), "r"(1u) : "memory");
        const unsigned target = (v / NCTA_DIR + 1u) * NCTA_DIR;
        for (;;) {
            unsigned cv;
            asm volatile("ld.acquire.gpu.global.u32 %0, [%1];"
                         : "=r"(cv) : "l"(t) : "memory");
            if ((int)(cv - target) >= 0) break;
            __nanosleep(64);
        }
    }
    __syncthreads();
}

__device__ __forceinline__ float sigf(float x) { return 1.0f / (1.0f + __expf(-x)); }
__device__ __forceinline__ float tanhfast(float x) { return 2.0f * sigf(2.0f * x) - 1.0f; }

__global__ void __launch_bounds__(256, 1)
scan_kernel(const float* __restrict__ feats_mask,
            const float* __restrict__ whh_lr, const float* __restrict__ bhh_lr,
            const float* __restrict__ whh_rl, const float* __restrict__ bhh_rl,
            float* __restrict__ out)
{
    extern __shared__ char smem[];
    char*     Ahi  = smem + OFF_AHI;
    char*     Alo  = smem + OFF_ALO;
    char*     Bhi  = smem + OFF_BHI;
    char*     Blo  = smem + OFF_BLO;
    float*    redF = (float*)(smem + OFF_RED);
    float*    outs = (float*)(smem + OFF_OUTS);
    unsigned* ohx  = (unsigned*)(smem + OFF_OHX);

    const int tid   = threadIdx.x;
    const int lane  = tid & 31;
    const int wid   = tid >> 5;
    const int dir   = blockIdx.x >> 6;
    const int slice = blockIdx.x & 63;
    const int j0    = slice * HS;
    const int wm    = wid >> 1;
    const int wk    = wid & 1;

    const float* __restrict__ whh = dir ? whh_rl : whh_lr;
    const float* __restrict__ bhh = dir ? bhh_rl : bhh_lr;
    const float* __restrict__ gxbase = g_gx + (size_t)dir * ((size_t)BDIM * LDIM * G3);
    unsigned* __restrict__ hx = g_hx + (size_t)dir * 2 * BDIM * HDIM;

    for (int idx = tid; idx < 6144; idx += 256) {
        const int c = idx >> 8, kp = idx & 255, k = kp * 2;
        const int g = c >> 3, u = c & 7;
        const float* wr = whh + (size_t)(g * HDIM + j0 + u) * HDIM + k;
        const float w0 = wr[0], w1 = wr[1];
        const float h0 = bf16_hi(w0), h1 = bf16_hi(w1);
        *(unsigned*)(Bhi + c * APITCH + k * 2) = pack_bf16x2(w0, w1);
        *(unsigned*)(Blo + c * APITCH + k * 2) = pack_bf16x2(w0 - h0, w1 - h1);
    }

    const int ub = tid >> 6;             // 0..3
    const int bb = tid & 63;
    float bias[2][3];
    #pragma unroll
    for (int q = 0; q < 2; ++q)
        #pragma unroll
        for (int g = 0; g < 3; ++g)
            bias[q][g] = bhh[g * HDIM + j0 + ub + q * 4];

    float hp0 = 0.0f, hp1 = 0.0f;
    for (int idx = tid; idx < 512; idx += 256) {
        const int b = idx >> 3, u = idx & 7;
        hx[(size_t)b * HDIM + j0 + u] = 0u;
    }

    const int bsrow = tid & 63;
    const int kq    = tid >> 6;
    const int ob    = tid >> 2;
    const int oq    = tid & 3;

    grid_barrier(dir);

    for (int s = 0; s < LDIM; ++s) {
        const int cur = s & 1, nxt = cur ^ 1;
        const int t_in = dir ? (LDIM - 1 - s) : s;

        // ---- gx (coalesced: [t][g][u][b], b innermost) + mask ----
        float gxr[2][3];
        #pragma unroll
        for (int q = 0; q < 2; ++q)
            #pragma unroll
            for (int g = 0; g < 3; ++g)
                gxr[q][g] = gxbase[((size_t)(t_in * 3 + g) * 512 + j0 + ub + q * 4) * 64 + bb];
        const float mk = feats_mask[(size_t)bb * LDIM + t_in];

        // ---- stage h: global u32(hi|lo) -> Ahi/Alo bf16 tiles ----
        {
            const unsigned* src = hx + (size_t)cur * BDIM * HDIM
                                     + (size_t)bsrow * HDIM + kq * 128;
            char* dhi = Ahi + bsrow * APITCH + kq * 256;
            char* dlo = Alo + bsrow * APITCH + kq * 256;
            #pragma unroll 8
            for (int i = 0; i < 16; ++i) {
                uint4 r0 = ((const uint4*)src)[i * 2];
                uint4 r1 = ((const uint4*)src)[i * 2 + 1];
                uint4 hi, lo;
                hi.x = prmt(r0.x, r0.y, 0x5410); lo.x = prmt(r0.x, r0.y, 0x7632);
                hi.y = prmt(r0.z, r0.w, 0x5410); lo.y = prmt(r0.z, r0.w, 0x7632);
                hi.z = prmt(r1.x, r1.y, 0x5410); lo.z = prmt(r1.x, r1.y, 0x7632);
                hi.w = prmt(r1.z, r1.w, 0x5410); lo.w = prmt(r1.z, r1.w, 0x7632);
                *(uint4*)(dhi + i * 16) = hi;
                *(uint4*)(dlo + i * 16) = lo;
            }
        }
        __syncthreads();

        // ---- mma: G[64,24] partials over this warp's k-half ----
        float acc[3][4];
        #pragma unroll
        for (int nt = 0; nt < 3; ++nt)
            #pragma unroll
            for (int q = 0; q < 4; ++q) acc[nt][q] = 0.0f;

        {
            const int arow  = (wm * 16 + (lane & 15)) * APITCH;
            const int brow0 = (lane & 15) * APITCH;
            const int brow1 = (16 + (lane & 15)) * APITCH;
            #pragma unroll 4
            for (int i = 0; i < 16; ++i) {
                const int kb = (wk * 256 + i * 16 + (lane >> 4) * 8) * 2;
                unsigned aH[4], aL[4], bh0[4], bh1[4], bl0[4], bl1[4];
                ldsm4(aH[0], aH[1], aH[2], aH[3], Ahi + arow + kb);
                ldsm4(aL[0], aL[1], aL[2], aL[3], Alo + arow + kb);
                ldsm4(bh0[0], bh0[1], bh0[2], bh0[3], Bhi + brow0 + kb);
                ldsm4(bh1[0], bh1[1], bh1[2], bh1[3], Bhi + brow1 + kb);
                ldsm4(bl0[0], bl0[1], bl0[2], bl0[3], Blo + brow0 + kb);
                ldsm4(bl1[0], bl1[1], bl1[2], bl1[3], Blo + brow1 + kb);
                mma16816(acc[0], aH, bh0[0], bh0[2]);
                mma16816(acc[0], aH, bl0[0], bl0[2]);
                mma16816(acc[0], aL, bh0[0], bh0[2]);
                mma16816(acc[1], aH, bh0[1], bh0[3]);
                mma16816(acc[1], aH, bl0[1], bl0[3]);
                mma16816(acc[1], aL, bh0[1], bh0[3]);
                mma16816(acc[2], aH, bh1[0], bh1[2]);
                mma16816(acc[2], aH, bl1[0], bl1[2]);
                mma16816(acc[2], aL, bh1[0], bh1[2]);
            }
        }

        {
            const int rA = wk * 64 + wm * 16 + (lane >> 2);
            const int cA = (lane & 3) * 2;
            #pragma unroll
            for (int nt = 0; nt < 3; ++nt) {
                float* p = redF + rA * 26 + nt * 8 + cA;
                p[0] = acc[nt][0]; p[1] = acc[nt][1];
                p[8 * 26] = acc[nt][2]; p[8 * 26 + 1] = acc[nt][3];
            }
        }
        __syncthreads();

        // ---- gates (fp32) for (ub,bb) and (ub+4,bb) ----
        {
            const float* r0 = redF + bb * 26;
            const float* r1 = redF + (64 + bb) * 26;

            const int u0 = ub;
            float ghr = r0[u0] + r1[u0] + bias[0][0];
            float ghz = r0[8 + u0] + r1[8 + u0] + bias[0][1];
            float ghn = r0[16 + u0] + r1[16 + u0] + bias[0][2];
            float rr = sigf(gxr[0][0] + ghr);
            float zz = sigf(gxr[0][1] + ghz);
            float nn = tanhfast(gxr[0][2] + rr * ghn);
            float hn = (1.0f - zz) * nn + zz * hp0;
            hn = mk * hn + (1.0f - mk) * hp0;
            hp0 = hn;
            outs[bb * 8 + u0] = hn;
            ohx[bb * 8 + u0]  = pack_bf16x2(hn, hn - bf16_hi(hn));

            const int u1 = ub + 4;
            ghr = r0[u1] + r1[u1] + bias[1][0];
            ghz = r0[8 + u1] + r1[8 + u1] + bias[1][1];
            ghn = r0[16 + u1] + r1[16 + u1] + bias[1][2];
            rr = sigf(gxr[1][0] + ghr);
            zz = sigf(gxr[1][1] + ghz);
            nn = tanhfast(gxr[1][2] + rr * ghn);
            hn = (1.0f - zz) * nn + zz * hp1;
            hn = mk * hn + (1.0f - mk) * hp1;
            hp1 = hn;
            outs[bb * 8 + u1] = hn;
            ohx[bb * 8 + u1]  = pack_bf16x2(hn, hn - bf16_hi(hn));
        }
        __syncthreads();

        // ---- coalesced stores: out + next-step hx ----
        {
            float2 ov = *(const float2*)(outs + ob * 8 + oq * 2);
            *(float2*)(out + ((size_t)ob * LDIM + t_in) * (2 * HDIM)
                       + dir * HDIM + j0 + oq * 2) = ov;
            uint2 hv = *(const uint2*)(ohx + ob * 8 + oq * 2);
            *(uint2*)(hx + (size_t)nxt * BDIM * HDIM
                      + (size_t)ob * HDIM + j0 + oq * 2) = hv;
        }

        grid_barrier(dir);
    }
}

// =====================================================================
extern "C" void kernel_launch(void* const* d_in, const int* in_sizes, int n_in,
                              void* d_out, int out_size)
{
    const float* feats      = (const float*)d_in[0];
    const float* feats_mask = (const float*)d_in[1];
    const float* w_ih_lr    = (const float*)d_in[2];
    const float* w_hh_lr    = (const float*)d_in[3];
    const float* b_ih_lr    = (const float*)d_in[4];
    const float* b_hh_lr    = (const float*)d_in[5];
    const float* w_ih_rl    = (const float*)d_in[6];
    const float* w_hh_rl    = (const float*)d_in[7];
    const float* b_ih_rl    = (const float*)d_in[8];
    const float* b_hh_rl    = (const float*)d_in[9];
    float* out = (float*)d_out;

    cudaFuncSetAttribute(scan_kernel, cudaFuncAttributeMaxDynamicSharedMemorySize,
                         SM_BYTES);

    convx_kernel<<<32768, 256>>>(feats);
    convw_kernel<<<1536, 256>>>(w_ih_lr, w_ih_rl);

    dim3 ggrid(G3 / 128, (BDIM * LDIM) / 128, 2);
    hgemm_kernel<<<ggrid, 256>>>(b_ih_lr, b_ih_rl);

    scan_kernel<<<2 * NCTA_DIR, 256, SM_BYTES>>>(
        feats_mask, w_hh_lr, b_hh_lr, w_hh_rl, b_hh_rl, out);
}

// round 11
// speedup vs baseline: 1.2045x; 1.2045x over previous
#include <cuda_runtime.h>
#include <cuda_bf16.h>
#include <math.h>

#define BDIM   64
#define LDIM   1024
#define INDIM  512
#define HDIM   512
#define G3     1536
#define NCTA_DIR 64
#define HS     8

typedef unsigned long long u64;

// ---------- static device scratch (no allocations) ----------
__device__ float g_gx[(size_t)2 * BDIM * LDIM * G3];          // [dir][b][l][1536] fp32
__device__ __nv_bfloat16 g_xb[(size_t)BDIM * LDIM * 1536];    // A' = [hi|hi|lo]
__device__ __nv_bfloat16 g_wb[(size_t)2 * 1536 * 1536];       // B' = [hi|lo|hi] per dir
__device__ unsigned g_hx[2 * 2 * BDIM * HDIM];                // [dir][buf][b][k] bf16 hi|lo
__device__ unsigned g_ticket2[2][32];                         // per-dir tickets, padded

// =====================================================================
// helpers
// =====================================================================
__device__ __forceinline__ unsigned pack_bf16x2(float a, float b)
{
    unsigned lo = (unsigned)__bfloat16_as_ushort(__float2bfloat16(a));
    unsigned hi = (unsigned)__bfloat16_as_ushort(__float2bfloat16(b));
    return lo | (hi << 16);
}
__device__ __forceinline__ float bf16_hi(float v)
{
    return __bfloat162float(__float2bfloat16(v));
}
__device__ __forceinline__ unsigned prmt(unsigned a, unsigned b, unsigned sel)
{
    unsigned d;
    asm("prmt.b32 %0, %1, %2, %3;" : "=r"(d) : "r"(a), "r"(b), "r"(sel));
    return d;
}

__global__ void convx_kernel(const float* __restrict__ X)
{
    const size_t i = (size_t)blockIdx.x * 256 + threadIdx.x;   // < 8388608
    float4 v = ((const float4*)X)[i];
    const size_t m  = i >> 7;
    const int    kq = (int)(i & 127);
    uint2 h, lo;
    h.x  = pack_bf16x2(v.x, v.y);
    h.y  = pack_bf16x2(v.z, v.w);
    lo.x = pack_bf16x2(v.x - bf16_hi(v.x), v.y - bf16_hi(v.y));
    lo.y = pack_bf16x2(v.z - bf16_hi(v.z), v.w - bf16_hi(v.w));
    __nv_bfloat16* d = g_xb + m * 1536 + kq * 4;
    *(uint2*)(d)        = h;
    *(uint2*)(d + 512)  = h;
    *(uint2*)(d + 1024) = lo;
}

__global__ void convw_kernel(const float* __restrict__ Wlr, const float* __restrict__ Wrl)
{
    const int i   = blockIdx.x * 256 + threadIdx.x;            // < 393216
    const int dir = i / 196608;
    const int rem = i - dir * 196608;
    const int n   = rem >> 7;
    const int kq  = rem & 127;
    const float* W = dir ? Wrl : Wlr;
    float4 v = ((const float4*)W)[rem];
    uint2 h, lo;
    h.x  = pack_bf16x2(v.x, v.y);
    h.y  = pack_bf16x2(v.z, v.w);
    lo.x = pack_bf16x2(v.x - bf16_hi(v.x), v.y - bf16_hi(v.y));
    lo.y = pack_bf16x2(v.z - bf16_hi(v.z), v.w - bf16_hi(v.w));
    __nv_bfloat16* d = g_wb + (size_t)dir * 1536 * 1536 + (size_t)n * 1536 + kq * 4;
    *(uint2*)(d)        = h;
    *(uint2*)(d + 512)  = lo;
    *(uint2*)(d + 1024) = h;
}

// =====================================================================
// mma primitives
// =====================================================================
__device__ __forceinline__ void ldsm4(unsigned& r0, unsigned& r1, unsigned& r2, unsigned& r3,
                                      const void* p)
{
    unsigned a = (unsigned)__cvta_generic_to_shared(p);
    asm volatile("ldmatrix.sync.aligned.m8n8.x4.shared.b16 {%0,%1,%2,%3}, [%4];"
                 : "=r"(r0), "=r"(r1), "=r"(r2), "=r"(r3) : "r"(a));
}
__device__ __forceinline__ void mma16816(float* c, const unsigned* a, unsigned b0, unsigned b1)
{
    asm volatile("mma.sync.aligned.m16n8k16.row.col.f32.bf16.bf16.f32 "
                 "{%0,%1,%2,%3}, {%4,%5,%6,%7}, {%8,%9}, {%0,%1,%2,%3};"
                 : "+f"(c[0]), "+f"(c[1]), "+f"(c[2]), "+f"(c[3])
                 : "r"(a[0]), "r"(a[1]), "r"(a[2]), "r"(a[3]), "r"(b0), "r"(b1));
}

// =====================================================================
// Input-projection GEMM (R8 version, contiguous epilogue)
// =====================================================================
__global__ void __launch_bounds__(256, 1)
hgemm_kernel(const float* __restrict__ blr, const float* __restrict__ brl)
{
    __shared__ __nv_bfloat16 As[2][128][40];
    __shared__ __nv_bfloat16 Bs[2][128][40];

    const int tid  = threadIdx.x;
    const int lane = tid & 31;
    const int wid  = tid >> 5;
    const int dir  = blockIdx.z;
    const int m0   = blockIdx.y * 128;
    const int n0   = blockIdx.x * 128;
    const int wm   = wid >> 1;
    const int wn   = wid & 1;

    const int row0 = tid >> 2;
    const int cc   = tid & 3;

    const __nv_bfloat16* ga0 = g_xb + (size_t)(m0 + row0) * 1536 + cc * 8;
    const __nv_bfloat16* gb0 = g_wb + (size_t)dir * 1536 * 1536
                                    + (size_t)(n0 + row0) * 1536 + cc * 8;

    uint4 av0 = *(const uint4*)ga0;
    uint4 av1 = *(const uint4*)(ga0 + (size_t)64 * 1536);
    uint4 bv0 = *(const uint4*)gb0;
    uint4 bv1 = *(const uint4*)(gb0 + (size_t)64 * 1536);
    *(uint4*)&As[0][row0][cc * 8]      = av0;
    *(uint4*)&As[0][row0 + 64][cc * 8] = av1;
    *(uint4*)&Bs[0][row0][cc * 8]      = bv0;
    *(uint4*)&Bs[0][row0 + 64][cc * 8] = bv1;
    __syncthreads();

    float acc[2][8][4];
    #pragma unroll
    for (int mt = 0; mt < 2; ++mt)
        #pragma unroll
        for (int nt = 0; nt < 8; ++nt)
            #pragma unroll
            for (int q = 0; q < 4; ++q) acc[mt][nt][q] = 0.0f;

    #pragma unroll 1
    for (int kt = 0; kt < 48; ++kt) {
        const int buf = kt & 1;
        if (kt < 47) {
            const int off = (kt + 1) * 32;
            av0 = *(const uint4*)(ga0 + off);
            av1 = *(const uint4*)(ga0 + (size_t)64 * 1536 + off);
            bv0 = *(const uint4*)(gb0 + off);
            bv1 = *(const uint4*)(gb0 + (size_t)64 * 1536 + off);
        }
        #pragma unroll
        for (int ks = 0; ks < 2; ++ks) {
            unsigned af[2][4], bfr[4][4];
            #pragma unroll
            for (int mt = 0; mt < 2; ++mt)
                ldsm4(af[mt][0], af[mt][1], af[mt][2], af[mt][3],
                      &As[buf][wm * 32 + mt * 16 + (lane & 15)][ks * 16 + (lane >> 4) * 8]);
            #pragma unroll
            for (int nt2 = 0; nt2 < 4; ++nt2)
                ldsm4(bfr[nt2][0], bfr[nt2][1], bfr[nt2][2], bfr[nt2][3],
                      &Bs[buf][wn * 64 + nt2 * 16 + (lane & 15)][ks * 16 + (lane >> 4) * 8]);
            #pragma unroll
            for (int mt = 0; mt < 2; ++mt)
                #pragma unroll
                for (int nt = 0; nt < 8; ++nt)
                    mma16816(acc[mt][nt], af[mt],
                             bfr[nt >> 1][nt & 1], bfr[nt >> 1][2 + (nt & 1)]);
        }
        if (kt < 47) {
            const int nb = buf ^ 1;
            *(uint4*)&As[nb][row0][cc * 8]      = av0;
            *(uint4*)&As[nb][row0 + 64][cc * 8] = av1;
            *(uint4*)&Bs[nb][row0][cc * 8]      = bv0;
            *(uint4*)&Bs[nb][row0 + 64][cc * 8] = bv1;
        }
        __syncthreads();
    }

    const float* bia = dir ? brl : blr;
    float* C = g_gx + (size_t)dir * ((size_t)BDIM * LDIM * G3);
    #pragma unroll
    for (int mt = 0; mt < 2; ++mt) {
        #pragma unroll
        for (int nt = 0; nt < 8; ++nt) {
            const int r  = m0 + wm * 32 + mt * 16 + (lane >> 2);
            const int nc = n0 + wn * 64 + nt * 8 + (lane & 3) * 2;
            const float bx = bia[nc], by = bia[nc + 1];
            float* Cp = C + (size_t)r * G3 + nc;
            *(float2*)Cp = make_float2(acc[mt][nt][0] + bx, acc[mt][nt][1] + by);
            *(float2*)(Cp + (size_t)8 * G3) =
                make_float2(acc[mt][nt][2] + bx, acc[mt][nt][3] + by);
        }
    }
}

// =====================================================================
// Tensor-core recurrent scan, v3: B fragments register-resident.
// 128 CTAs (64/dir) x 256 threads. Warps: mg = wid&1 (rows mg*32..+32),
// kq4 = wid>>1 (k-quarter). Split arrive/wait barrier; gx prefetch
// overlaps the barrier arrival spread.
// =====================================================================
#define APITCH   1040
#define OFF_AHI  0
#define OFF_ALO  66560
#define OFF_BHI  0            // overlay (B used only at init)
#define OFF_BLO  33280
#define OFF_RED  133120       // float[4][64][26]
#define OFF_OUTS 159744       // float[512]
#define OFF_OHX  161792       // unsigned[512]
#define SM_BYTES 163840

__device__ __forceinline__ unsigned grid_arrive(int dir)
{
    __syncthreads();
    unsigned tgt = 0;
    if (threadIdx.x == 0) {
        unsigned v;
        asm volatile("atom.release.gpu.global.add.u32 %0, [%1], %2;"
                     : "=r"(v) : "l"(&g_ticket2[dir][0]), "r"(1u) : "memory");
        tgt = (v / NCTA_DIR + 1u) * NCTA_DIR;
    }
    return tgt;
}
__device__ __forceinline__ void grid_wait(int dir, unsigned tgt)
{
    if (threadIdx.x == 0) {
        for (;;) {
            unsigned cv;
            asm volatile("ld.acquire.gpu.global.u32 %0, [%1];"
                         : "=r"(cv) : "l"(&g_ticket2[dir][0]) : "memory");
            if ((int)(cv - tgt) >= 0) break;
        }
    }
    __syncthreads();
}

__device__ __forceinline__ float sigf(float x) { return 1.0f / (1.0f + __expf(-x)); }
__device__ __forceinline__ float tanhfast(float x) { return 2.0f * sigf(2.0f * x) - 1.0f; }

__global__ void __launch_bounds__(256, 1)
scan_kernel(const float* __restrict__ feats_mask,
            const float* __restrict__ whh_lr, const float* __restrict__ bhh_lr,
            const float* __restrict__ whh_rl, const float* __restrict__ bhh_rl,
            float* __restrict__ out)
{
    extern __shared__ char smem[];
    char*     Ahi  = smem + OFF_AHI;
    char*     Alo  = smem + OFF_ALO;
    float*    redF = (float*)(smem + OFF_RED);
    float*    outs = (float*)(smem + OFF_OUTS);
    unsigned* ohx  = (unsigned*)(smem + OFF_OHX);

    const int tid   = threadIdx.x;
    const int lane  = tid & 31;
    const int wid   = tid >> 5;
    const int dir   = blockIdx.x >> 6;
    const int slice = blockIdx.x & 63;
    const int j0    = slice * HS;
    const int mg    = wid & 1;           // m-group: rows mg*32 .. +32
    const int kq4   = wid >> 1;          // k-quarter: [kq4*128, +128)

    const float* __restrict__ whh = dir ? whh_rl : whh_lr;
    const float* __restrict__ bhh = dir ? bhh_rl : bhh_lr;
    const float* __restrict__ gxbase = g_gx + (size_t)dir * ((size_t)BDIM * LDIM * G3);
    unsigned* __restrict__ hx = g_hx + (size_t)dir * 2 * BDIM * HDIM;

    // ---- build B tiles (overlayed in A region, used once) ----
    {
        char* Bhi = smem + OFF_BHI;
        char* Blo = smem + OFF_BLO;
        for (int idx = tid; idx < 6144; idx += 256) {
            const int c = idx >> 8, kp = idx & 255, k = kp * 2;
            const int g = c >> 3, u = c & 7;
            const float* wr = whh + (size_t)(g * HDIM + j0 + u) * HDIM + k;
            const float w0 = wr[0], w1 = wr[1];
            const float h0 = bf16_hi(w0), h1 = bf16_hi(w1);
            *(unsigned*)(Bhi + c * APITCH + k * 2) = pack_bf16x2(w0, w1);
            *(unsigned*)(Blo + c * APITCH + k * 2) = pack_bf16x2(w0 - h0, w1 - h1);
        }
    }
    __syncthreads();

    // ---- preload B fragments into registers (loop-invariant) ----
    unsigned bh[8][6], bl[8][6];
    {
        const char* Bhi = smem + OFF_BHI;
        const char* Blo = smem + OFF_BLO;
        #pragma unroll
        for (int i = 0; i < 8; ++i) {
            const int kb = (kq4 * 128 + i * 16 + (lane >> 4) * 8) * 2;
            unsigned t0, t1, t2, t3, s0, s1, s2, s3;
            ldsm4(t0, t1, t2, t3, Bhi + (lane & 15) * APITCH + kb);
            ldsm4(s0, s1, s2, s3, Bhi + (16 + (lane & 15)) * APITCH + kb);
            bh[i][0] = t0; bh[i][1] = t1; bh[i][2] = t2; bh[i][3] = t3;
            bh[i][4] = s0; bh[i][5] = s2;
            ldsm4(t0, t1, t2, t3, Blo + (lane & 15) * APITCH + kb);
            ldsm4(s0, s1, s2, s3, Blo + (16 + (lane & 15)) * APITCH + kb);
            bl[i][0] = t0; bl[i][1] = t1; bl[i][2] = t2; bl[i][3] = t3;
            bl[i][4] = s0; bl[i][5] = s2;
        }
    }
    __syncthreads();   // before A staging reuses the overlay region

    // ---- gate-phase mapping ----
    const int ub = tid >> 6;             // 0..3
    const int bb = tid & 63;
    float bias[2][3];
    #pragma unroll
    for (int q = 0; q < 2; ++q)
        #pragma unroll
        for (int g = 0; g < 3; ++g)
            bias[q][g] = bhh[g * HDIM + j0 + ub + q * 4];

    float hp0 = 0.0f, hp1 = 0.0f;
    for (int idx = tid; idx < 512; idx += 256) {
        const int b = idx >> 3, u = idx & 7;
        hx[(size_t)b * HDIM + j0 + u] = 0u;
    }

    const int bsrow = tid & 63;
    const int kq    = tid >> 6;
    const int ob    = tid >> 2;
    const int oq    = tid & 3;

    unsigned bar_tgt = grid_arrive(dir);

    for (int s = 0; s < LDIM; ++s) {
        const int cur = s & 1, nxt = cur ^ 1;
        const int t_in = dir ? (LDIM - 1 - s) : s;

        // ---- gx + mask prefetch: overlaps barrier arrival spread ----
        float gxr[2][3];
        #pragma unroll
        for (int q = 0; q < 2; ++q)
            #pragma unroll
            for (int g = 0; g < 3; ++g)
                gxr[q][g] = gxbase[((size_t)bb * LDIM + t_in) * G3
                                   + g * HDIM + j0 + ub + q * 4];
        const float mk = feats_mask[(size_t)bb * LDIM + t_in];

        grid_wait(dir, bar_tgt);         // h(s) published grid-wide

        // ---- stage h: global u32(hi|lo) -> Ahi/Alo bf16 tiles ----
        {
            const unsigned* src = hx + (size_t)cur * BDIM * HDIM
                                     + (size_t)bsrow * HDIM + kq * 128;
            char* dhi = Ahi + bsrow * APITCH + kq * 256;
            char* dlo = Alo + bsrow * APITCH + kq * 256;
            #pragma unroll 8
            for (int i = 0; i < 16; ++i) {
                uint4 r0 = ((const uint4*)src)[i * 2];
                uint4 r1 = ((const uint4*)src)[i * 2 + 1];
                uint4 hi, lo;
                hi.x = prmt(r0.x, r0.y, 0x5410); lo.x = prmt(r0.x, r0.y, 0x7632);
                hi.y = prmt(r0.z, r0.w, 0x5410); lo.y = prmt(r0.z, r0.w, 0x7632);
                hi.z = prmt(r1.x, r1.y, 0x5410); lo.z = prmt(r1.x, r1.y, 0x7632);
                hi.w = prmt(r1.z, r1.w, 0x5410); lo.w = prmt(r1.z, r1.w, 0x7632);
                *(uint4*)(dhi + i * 16) = hi;
                *(uint4*)(dlo + i * 16) = lo;
            }
        }
        __syncthreads();

        // ---- mma: rows [mg*32,+32), k-quarter kq4, 24 cols ----
        float acc[2][3][4];
        #pragma unroll
        for (int mt = 0; mt < 2; ++mt)
            #pragma unroll
            for (int nt = 0; nt < 3; ++nt)
                #pragma unroll
                for (int q = 0; q < 4; ++q) acc[mt][nt][q] = 0.0f;

        {
            const int arow = (mg * 32 + (lane & 15)) * APITCH;
            #pragma unroll
            for (int i = 0; i < 8; ++i) {
                const int kb = (kq4 * 128 + i * 16 + (lane >> 4) * 8) * 2;
                unsigned ah0[4], ah1[4], al0[4], al1[4];
                ldsm4(ah0[0], ah0[1], ah0[2], ah0[3], Ahi + arow + kb);
                ldsm4(ah1[0], ah1[1], ah1[2], ah1[3], Ahi + arow + 16 * APITCH + kb);
                ldsm4(al0[0], al0[1], al0[2], al0[3], Alo + arow + kb);
                ldsm4(al1[0], al1[1], al1[2], al1[3], Alo + arow + 16 * APITCH + kb);
                // mt = 0
                mma16816(acc[0][0], ah0, bh[i][0], bh[i][2]);
                mma16816(acc[0][0], ah0, bl[i][0], bl[i][2]);
                mma16816(acc[0][0], al0, bh[i][0], bh[i][2]);
                mma16816(acc[0][1], ah0, bh[i][1], bh[i][3]);
                mma16816(acc[0][1], ah0, bl[i][1], bl[i][3]);
                mma16816(acc[0][1], al0, bh[i][1], bh[i][3]);
                mma16816(acc[0][2], ah0, bh[i][4], bh[i][5]);
                mma16816(acc[0][2], ah0, bl[i][4], bl[i][5]);
                mma16816(acc[0][2], al0, bh[i][4], bh[i][5]);
                // mt = 1
                mma16816(acc[1][0], ah1, bh[i][0], bh[i][2]);
                mma16816(acc[1][0], ah1, bl[i][0], bl[i][2]);
                mma16816(acc[1][0], al1, bh[i][0], bh[i][2]);
                mma16816(acc[1][1], ah1, bh[i][1], bh[i][3]);
                mma16816(acc[1][1], ah1, bl[i][1], bl[i][3]);
                mma16816(acc[1][1], al1, bh[i][1], bh[i][3]);
                mma16816(acc[1][2], ah1, bh[i][4], bh[i][5]);
                mma16816(acc[1][2], ah1, bl[i][4], bl[i][5]);
                mma16816(acc[1][2], al1, bh[i][4], bh[i][5]);
            }
        }

        // ---- write k-partials: redF[kq4][row(batch)][col] ----
        {
            const int rbase = mg * 32 + (lane >> 2);
            #pragma unroll
            for (int mt = 0; mt < 2; ++mt) {
                #pragma unroll
                for (int nt = 0; nt < 3; ++nt) {
                    float* p = redF + (kq4 * 64 + rbase + mt * 16) * 26
                             + nt * 8 + (lane & 3) * 2;
                    p[0] = acc[mt][nt][0]; p[1] = acc[mt][nt][1];
                    p[8 * 26] = acc[mt][nt][2]; p[8 * 26 + 1] = acc[mt][nt][3];
                }
            }
        }
        __syncthreads();

        // ---- gates (fp32): sum 4 k-partials ----
        {
            const float* r0 = redF + bb * 26;
            const float* r1 = redF + (64 + bb) * 26;
            const float* r2 = redF + (128 + bb) * 26;
            const float* r3 = redF + (192 + bb) * 26;

            const int u0 = ub;
            float ghr = r0[u0] + r1[u0] + r2[u0] + r3[u0] + bias[0][0];
            float ghz = r0[8+u0] + r1[8+u0] + r2[8+u0] + r3[8+u0] + bias[0][1];
            float ghn = r0[16+u0] + r1[16+u0] + r2[16+u0] + r3[16+u0] + bias[0][2];
            float rr = sigf(gxr[0][0] + ghr);
            float zz = sigf(gxr[0][1] + ghz);
            float nn = tanhfast(gxr[0][2] + rr * ghn);
            float hn = (1.0f - zz) * nn + zz * hp0;
            hn = mk * hn + (1.0f - mk) * hp0;
            hp0 = hn;
            outs[bb * 8 + u0] = hn;
            ohx[bb * 8 + u0]  = pack_bf16x2(hn, hn - bf16_hi(hn));

            const int u1 = ub + 4;
            ghr = r0[u1] + r1[u1] + r2[u1] + r3[u1] + bias[1][0];
            ghz = r0[8+u1] + r1[8+u1] + r2[8+u1] + r3[8+u1] + bias[1][1];
            ghn = r0[16+u1] + r1[16+u1] + r2[16+u1] + r3[16+u1] + bias[1][2];
            rr = sigf(gxr[1][0] + ghr);
            zz = sigf(gxr[1][1] + ghz);
            nn = tanhfast(gxr[1][2] + rr * ghn);
            hn = (1.0f - zz) * nn + zz * hp1;
            hn = mk * hn + (1.0f - mk) * hp1;
            hp1 = hn;
            outs[bb * 8 + u1] = hn;
            ohx[bb * 8 + u1]  = pack_bf16x2(hn, hn - bf16_hi(hn));
        }
        __syncthreads();

        // ---- coalesced stores: out + next-step hx, then arrive ----
        {
            float2 ov = *(const float2*)(outs + ob * 8 + oq * 2);
            *(float2*)(out + ((size_t)ob * LDIM + t_in) * (2 * HDIM)
                       + dir * HDIM + j0 + oq * 2) = ov;
            uint2 hv = *(const uint2*)(ohx + ob * 8 + oq * 2);
            *(uint2*)(hx + (size_t)nxt * BDIM * HDIM
                      + (size_t)ob * HDIM + j0 + oq * 2) = hv;
        }

        bar_tgt = grid_arrive(dir);
    }
}

// =====================================================================
extern "C" void kernel_launch(void* const* d_in, const int* in_sizes, int n_in,
                              void* d_out, int out_size)
{
    const float* feats      = (const float*)d_in[0];
    const float* feats_mask = (const float*)d_in[1];
    const float* w_ih_lr    = (const float*)d_in[2];
    const float* w_hh_lr    = (const float*)d_in[3];
    const float* b_ih_lr    = (const float*)d_in[4];
    const float* b_hh_lr    = (const float*)d_in[5];
    const float* w_ih_rl    = (const float*)d_in[6];
    const float* w_hh_rl    = (const float*)d_in[7];
    const float* b_ih_rl    = (const float*)d_in[8];
    const float* b_hh_rl    = (const float*)d_in[9];
    float* out = (float*)d_out;

    cudaFuncSetAttribute(scan_kernel, cudaFuncAttributeMaxDynamicSharedMemorySize,
                         SM_BYTES);

    convx_kernel<<<32768, 256>>>(feats);
    convw_kernel<<<1536, 256>>>(w_ih_lr, w_ih_rl);

    dim3 ggrid(G3 / 128, (BDIM * LDIM) / 128, 2);
    hgemm_kernel<<<ggrid, 256>>>(b_ih_lr, b_ih_rl);

    scan_kernel<<<2 * NCTA_DIR, 256, SM_BYTES>>>(
        feats_mask, w_hh_lr, b_hh_lr, w_hh_rl, b_hh_rl, out);
}

// round 12
// speedup vs baseline: 1.6171x; 1.3426x over previous
#include <cuda_runtime.h>
#include <cuda_bf16.h>
#include <math.h>

#define BDIM   64
#define LDIM   1024
#define INDIM  512
#define HDIM   512
#define G3     1536
#define NCTA_DIR 64
#define HS     8

typedef unsigned long long u64;

// ---------- static device scratch (no allocations) ----------
__device__ float g_gx[(size_t)2 * BDIM * LDIM * G3];          // [dir][b][l][1536] fp32
__device__ __nv_bfloat16 g_xb[(size_t)BDIM * LDIM * 1536];    // A' = [hi|hi|lo]
__device__ __nv_bfloat16 g_wb[(size_t)2 * 1536 * 1536];       // B' = [hi|lo|hi] per dir
__device__ unsigned g_hx[2 * 2 * BDIM * HDIM];                // [dir][buf][b][k] bf16 hi|lo
__device__ unsigned g_ticket2[2][32];                         // per-dir tickets, padded

// =====================================================================
// helpers
// =====================================================================
__device__ __forceinline__ unsigned pack_bf16x2(float a, float b)
{
    unsigned lo = (unsigned)__bfloat16_as_ushort(__float2bfloat16(a));
    unsigned hi = (unsigned)__bfloat16_as_ushort(__float2bfloat16(b));
    return lo | (hi << 16);
}
__device__ __forceinline__ float bf16_hi(float v)
{
    return __bfloat162float(__float2bfloat16(v));
}
__device__ __forceinline__ unsigned prmt(unsigned a, unsigned b, unsigned sel)
{
    unsigned d;
    asm("prmt.b32 %0, %1, %2, %3;" : "=r"(d) : "r"(a), "r"(b), "r"(sel));
    return d;
}
// L2-only 8B load of two packed h words (coherence-safe for cross-SM data)
__device__ __forceinline__ uint2 ldg_cg_u2(const unsigned* p)
{
    uint2 v;
    asm volatile("ld.global.cg.v2.u32 {%0,%1}, [%2];"
                 : "=r"(v.x), "=r"(v.y) : "l"(p));
    return v;
}

__global__ void convx_kernel(const float* __restrict__ X)
{
    const size_t i = (size_t)blockIdx.x * 256 + threadIdx.x;   // < 8388608
    float4 v = ((const float4*)X)[i];
    const size_t m  = i >> 7;
    const int    kq = (int)(i & 127);
    uint2 h, lo;
    h.x  = pack_bf16x2(v.x, v.y);
    h.y  = pack_bf16x2(v.z, v.w);
    lo.x = pack_bf16x2(v.x - bf16_hi(v.x), v.y - bf16_hi(v.y));
    lo.y = pack_bf16x2(v.z - bf16_hi(v.z), v.w - bf16_hi(v.w));
    __nv_bfloat16* d = g_xb + m * 1536 + kq * 4;
    *(uint2*)(d)        = h;
    *(uint2*)(d + 512)  = h;
    *(uint2*)(d + 1024) = lo;
}

__global__ void convw_kernel(const float* __restrict__ Wlr, const float* __restrict__ Wrl)
{
    const int i   = blockIdx.x * 256 + threadIdx.x;            // < 393216
    const int dir = i / 196608;
    const int rem = i - dir * 196608;
    const int n   = rem >> 7;
    const int kq  = rem & 127;
    const float* W = dir ? Wrl : Wlr;
    float4 v = ((const float4*)W)[rem];
    uint2 h, lo;
    h.x  = pack_bf16x2(v.x, v.y);
    h.y  = pack_bf16x2(v.z, v.w);
    lo.x = pack_bf16x2(v.x - bf16_hi(v.x), v.y - bf16_hi(v.y));
    lo.y = pack_bf16x2(v.z - bf16_hi(v.z), v.w - bf16_hi(v.w));
    __nv_bfloat16* d = g_wb + (size_t)dir * 1536 * 1536 + (size_t)n * 1536 + kq * 4;
    *(uint2*)(d)        = h;
    *(uint2*)(d + 512)  = lo;
    *(uint2*)(d + 1024) = h;
}

// =====================================================================
// mma primitives
// =====================================================================
__device__ __forceinline__ void ldsm4(unsigned& r0, unsigned& r1, unsigned& r2, unsigned& r3,
                                      const void* p)
{
    unsigned a = (unsigned)__cvta_generic_to_shared(p);
    asm volatile("ldmatrix.sync.aligned.m8n8.x4.shared.b16 {%0,%1,%2,%3}, [%4];"
                 : "=r"(r0), "=r"(r1), "=r"(r2), "=r"(r3) : "r"(a));
}
__device__ __forceinline__ void mma16816(float* c, const unsigned* a, unsigned b0, unsigned b1)
{
    asm volatile("mma.sync.aligned.m16n8k16.row.col.f32.bf16.bf16.f32 "
                 "{%0,%1,%2,%3}, {%4,%5,%6,%7}, {%8,%9}, {%0,%1,%2,%3};"
                 : "+f"(c[0]), "+f"(c[1]), "+f"(c[2]), "+f"(c[3])
                 : "r"(a[0]), "r"(a[1]), "r"(a[2]), "r"(a[3]), "r"(b0), "r"(b1));
}

// =====================================================================
// Input-projection GEMM (unchanged)
// =====================================================================
__global__ void __launch_bounds__(256, 1)
hgemm_kernel(const float* __restrict__ blr, const float* __restrict__ brl)
{
    __shared__ __nv_bfloat16 As[2][128][40];
    __shared__ __nv_bfloat16 Bs[2][128][40];

    const int tid  = threadIdx.x;
    const int lane = tid & 31;
    const int wid  = tid >> 5;
    const int dir  = blockIdx.z;
    const int m0   = blockIdx.y * 128;
    const int n0   = blockIdx.x * 128;
    const int wm   = wid >> 1;
    const int wn   = wid & 1;

    const int row0 = tid >> 2;
    const int cc   = tid & 3;

    const __nv_bfloat16* ga0 = g_xb + (size_t)(m0 + row0) * 1536 + cc * 8;
    const __nv_bfloat16* gb0 = g_wb + (size_t)dir * 1536 * 1536
                                    + (size_t)(n0 + row0) * 1536 + cc * 8;

    uint4 av0 = *(const uint4*)ga0;
    uint4 av1 = *(const uint4*)(ga0 + (size_t)64 * 1536);
    uint4 bv0 = *(const uint4*)gb0;
    uint4 bv1 = *(const uint4*)(gb0 + (size_t)64 * 1536);
    *(uint4*)&As[0][row0][cc * 8]      = av0;
    *(uint4*)&As[0][row0 + 64][cc * 8] = av1;
    *(uint4*)&Bs[0][row0][cc * 8]      = bv0;
    *(uint4*)&Bs[0][row0 + 64][cc * 8] = bv1;
    __syncthreads();

    float acc[2][8][4];
    #pragma unroll
    for (int mt = 0; mt < 2; ++mt)
        #pragma unroll
        for (int nt = 0; nt < 8; ++nt)
            #pragma unroll
            for (int q = 0; q < 4; ++q) acc[mt][nt][q] = 0.0f;

    #pragma unroll 1
    for (int kt = 0; kt < 48; ++kt) {
        const int buf = kt & 1;
        if (kt < 47) {
            const int off = (kt + 1) * 32;
            av0 = *(const uint4*)(ga0 + off);
            av1 = *(const uint4*)(ga0 + (size_t)64 * 1536 + off);
            bv0 = *(const uint4*)(gb0 + off);
            bv1 = *(const uint4*)(gb0 + (size_t)64 * 1536 + off);
        }
        #pragma unroll
        for (int ks = 0; ks < 2; ++ks) {
            unsigned af[2][4], bfr[4][4];
            #pragma unroll
            for (int mt = 0; mt < 2; ++mt)
                ldsm4(af[mt][0], af[mt][1], af[mt][2], af[mt][3],
                      &As[buf][wm * 32 + mt * 16 + (lane & 15)][ks * 16 + (lane >> 4) * 8]);
            #pragma unroll
            for (int nt2 = 0; nt2 < 4; ++nt2)
                ldsm4(bfr[nt2][0], bfr[nt2][1], bfr[nt2][2], bfr[nt2][3],
                      &Bs[buf][wn * 64 + nt2 * 16 + (lane & 15)][ks * 16 + (lane >> 4) * 8]);
            #pragma unroll
            for (int mt = 0; mt < 2; ++mt)
                #pragma unroll
                for (int nt = 0; nt < 8; ++nt)
                    mma16816(acc[mt][nt], af[mt],
                             bfr[nt >> 1][nt & 1], bfr[nt >> 1][2 + (nt & 1)]);
        }
        if (kt < 47) {
            const int nb = buf ^ 1;
            *(uint4*)&As[nb][row0][cc * 8]      = av0;
            *(uint4*)&As[nb][row0 + 64][cc * 8] = av1;
            *(uint4*)&Bs[nb][row0][cc * 8]      = bv0;
            *(uint4*)&Bs[nb][row0 + 64][cc * 8] = bv1;
        }
        __syncthreads();
    }

    const float* bia = dir ? brl : blr;
    float* C = g_gx + (size_t)dir * ((size_t)BDIM * LDIM * G3);
    #pragma unroll
    for (int mt = 0; mt < 2; ++mt) {
        #pragma unroll
        for (int nt = 0; nt < 8; ++nt) {
            const int r  = m0 + wm * 32 + mt * 16 + (lane >> 2);
            const int nc = n0 + wn * 64 + nt * 8 + (lane & 3) * 2;
            const float bx = bia[nc], by = bia[nc + 1];
            float* Cp = C + (size_t)r * G3 + nc;
            *(float2*)Cp = make_float2(acc[mt][nt][0] + bx, acc[mt][nt][1] + by);
            *(float2*)(Cp + (size_t)8 * G3) =
                make_float2(acc[mt][nt][2] + bx, acc[mt][nt][3] + by);
        }
    }
}

// =====================================================================
// Tensor-core recurrent scan, v4: A fragments loaded straight from
// global (L2) with ld.cg — no smem staging, no pre-mma syncthreads.
// B fragments register-resident (R10). Backoff in barrier poll.
// =====================================================================
#define APITCH   1040
#define OFF_BHI  0            // B build area (init only)
#define OFF_BLO  24960
#define OFF_RED  49920        // float[4][64][26]
#define OFF_OUTS 76544        // float[512]
#define OFF_OHX  78592        // unsigned[512]
#define SM_BYTES 81920

__device__ __forceinline__ unsigned grid_arrive(int dir)
{
    __syncthreads();
    unsigned tgt = 0;
    if (threadIdx.x == 0) {
        unsigned v;
        asm volatile("atom.release.gpu.global.add.u32 %0, [%1], %2;"
                     : "=r"(v) : "l"(&g_ticket2[dir][0]), "r"(1u) : "memory");
        tgt = (v / NCTA_DIR + 1u) * NCTA_DIR;
    }
    return tgt;
}
__device__ __forceinline__ void grid_wait(int dir, unsigned tgt)
{
    if (threadIdx.x == 0) {
        for (;;) {
            unsigned cv;
            asm volatile("ld.acquire.gpu.global.u32 %0, [%1];"
                         : "=r"(cv) : "l"(&g_ticket2[dir][0]) : "memory");
            if ((int)(cv - tgt) >= 0) break;
            __nanosleep(40);
        }
    }
    __syncthreads();
}

__device__ __forceinline__ float sigf(float x) { return 1.0f / (1.0f + __expf(-x)); }
__device__ __forceinline__ float tanhfast(float x) { return 2.0f * sigf(2.0f * x) - 1.0f; }

__global__ void __launch_bounds__(256, 1)
scan_kernel(const float* __restrict__ feats_mask,
            const float* __restrict__ whh_lr, const float* __restrict__ bhh_lr,
            const float* __restrict__ whh_rl, const float* __restrict__ bhh_rl,
            float* __restrict__ out)
{
    extern __shared__ char smem[];
    float*    redF = (float*)(smem + OFF_RED);
    float*    outs = (float*)(smem + OFF_OUTS);
    unsigned* ohx  = (unsigned*)(smem + OFF_OHX);

    const int tid   = threadIdx.x;
    const int lane  = tid & 31;
    const int wid   = tid >> 5;
    const int dir   = blockIdx.x >> 6;
    const int slice = blockIdx.x & 63;
    const int j0    = slice * HS;
    const int mg    = wid & 1;           // m-group: rows mg*32 .. +32
    const int kq4   = wid >> 1;          // k-quarter: [kq4*128, +128)

    const float* __restrict__ whh = dir ? whh_rl : whh_lr;
    const float* __restrict__ bhh = dir ? bhh_rl : bhh_lr;
    const float* __restrict__ gxbase = g_gx + (size_t)dir * ((size_t)BDIM * LDIM * G3);
    unsigned* __restrict__ hx = g_hx + (size_t)dir * 2 * BDIM * HDIM;

    // ---- build B tiles in smem (init only) ----
    {
        char* Bhi = smem + OFF_BHI;
        char* Blo = smem + OFF_BLO;
        for (int idx = tid; idx < 6144; idx += 256) {
            const int c = idx >> 8, kp = idx & 255, k = kp * 2;
            const int g = c >> 3, u = c & 7;
            const float* wr = whh + (size_t)(g * HDIM + j0 + u) * HDIM + k;
            const float w0 = wr[0], w1 = wr[1];
            const float h0 = bf16_hi(w0), h1 = bf16_hi(w1);
            *(unsigned*)(Bhi + c * APITCH + k * 2) = pack_bf16x2(w0, w1);
            *(unsigned*)(Blo + c * APITCH + k * 2) = pack_bf16x2(w0 - h0, w1 - h1);
        }
    }
    __syncthreads();

    // ---- preload B fragments into registers (loop-invariant) ----
    unsigned bh[8][6], bl[8][6];
    {
        const char* Bhi = smem + OFF_BHI;
        const char* Blo = smem + OFF_BLO;
        #pragma unroll
        for (int i = 0; i < 8; ++i) {
            const int kb = (kq4 * 128 + i * 16 + (lane >> 4) * 8) * 2;
            unsigned t0, t1, t2, t3, s0, s1, s2, s3;
            ldsm4(t0, t1, t2, t3, Bhi + (lane & 15) * APITCH + kb);
            ldsm4(s0, s1, s2, s3, Bhi + (16 + (lane & 15)) * APITCH + kb);
            bh[i][0] = t0; bh[i][1] = t1; bh[i][2] = t2; bh[i][3] = t3;
            bh[i][4] = s0; bh[i][5] = s2;
            ldsm4(t0, t1, t2, t3, Blo + (lane & 15) * APITCH + kb);
            ldsm4(s0, s1, s2, s3, Blo + (16 + (lane & 15)) * APITCH + kb);
            bl[i][0] = t0; bl[i][1] = t1; bl[i][2] = t2; bl[i][3] = t3;
            bl[i][4] = s0; bl[i][5] = s2;
        }
    }

    // ---- gate-phase mapping ----
    const int ub = tid >> 6;             // 0..3
    const int bb = tid & 63;
    float bias[2][3];
    #pragma unroll
    for (int q = 0; q < 2; ++q)
        #pragma unroll
        for (int g = 0; g < 3; ++g)
            bias[q][g] = bhh[g * HDIM + j0 + ub + q * 4];

    float hp0 = 0.0f, hp1 = 0.0f;
    for (int idx = tid; idx < 512; idx += 256) {
        const int b = idx >> 3, u = idx & 7;
        hx[(size_t)b * HDIM + j0 + u] = 0u;
    }

    const int ob = tid >> 2;
    const int oq = tid & 3;

    // per-thread fragment source offsets (row, colpair from mma mapping)
    const int frow = mg * 32 + (lane >> 2);       // tile0 a0 row
    const int fcol = (lane & 3) * 2;

    unsigned bar_tgt = grid_arrive(dir);

    for (int s = 0; s < LDIM; ++s) {
        const int cur = s & 1, nxt = cur ^ 1;
        const int t_in = dir ? (LDIM - 1 - s) : s;

        // ---- gx + mask prefetch: overlaps barrier arrival spread ----
        float gxr[2][3];
        #pragma unroll
        for (int q = 0; q < 2; ++q)
            #pragma unroll
            for (int g = 0; g < 3; ++g)
                gxr[q][g] = gxbase[((size_t)bb * LDIM + t_in) * G3
                                   + g * HDIM + j0 + ub + q * 4];
        const float mk = feats_mask[(size_t)bb * LDIM + t_in];

        grid_wait(dir, bar_tgt);         // h(s) published grid-wide

        // ---- mma with direct-from-L2 A fragments ----
        float acc[2][3][4];
        #pragma unroll
        for (int mt = 0; mt < 2; ++mt)
            #pragma unroll
            for (int nt = 0; nt < 3; ++nt)
                #pragma unroll
                for (int q = 0; q < 4; ++q) acc[mt][nt][q] = 0.0f;

        {
            const unsigned* hsrc = hx + (size_t)cur * BDIM * HDIM;
            const unsigned* base0 = hsrc + (size_t)frow * HDIM + kq4 * 128 + fcol;
            #pragma unroll
            for (int i = 0; i < 8; ++i) {
                const unsigned* p = base0 + i * 16;
                // tile0 (rows frow, frow+8)
                uint2 p00 = ldg_cg_u2(p);                   // a0: (row, k..k+1)
                uint2 p01 = ldg_cg_u2(p + 8);               // a2: cols +8
                uint2 p10 = ldg_cg_u2(p + 8 * HDIM);        // a1: row +8
                uint2 p11 = ldg_cg_u2(p + 8 * HDIM + 8);    // a3
                // tile1 (rows +16)
                uint2 q00 = ldg_cg_u2(p + 16 * HDIM);
                uint2 q01 = ldg_cg_u2(p + 16 * HDIM + 8);
                uint2 q10 = ldg_cg_u2(p + 24 * HDIM);
                uint2 q11 = ldg_cg_u2(p + 24 * HDIM + 8);

                unsigned ah0[4], al0[4], ah1[4], al1[4];
                ah0[0] = prmt(p00.x, p00.y, 0x5410); al0[0] = prmt(p00.x, p00.y, 0x7632);
                ah0[1] = prmt(p10.x, p10.y, 0x5410); al0[1] = prmt(p10.x, p10.y, 0x7632);
                ah0[2] = prmt(p01.x, p01.y, 0x5410); al0[2] = prmt(p01.x, p01.y, 0x7632);
                ah0[3] = prmt(p11.x, p11.y, 0x5410); al0[3] = prmt(p11.x, p11.y, 0x7632);
                ah1[0] = prmt(q00.x, q00.y, 0x5410); al1[0] = prmt(q00.x, q00.y, 0x7632);
                ah1[1] = prmt(q10.x, q10.y, 0x5410); al1[1] = prmt(q10.x, q10.y, 0x7632);
                ah1[2] = prmt(q01.x, q01.y, 0x5410); al1[2] = prmt(q01.x, q01.y, 0x7632);
                ah1[3] = prmt(q11.x, q11.y, 0x5410); al1[3] = prmt(q11.x, q11.y, 0x7632);

                // mt = 0
                mma16816(acc[0][0], ah0, bh[i][0], bh[i][2]);
                mma16816(acc[0][0], ah0, bl[i][0], bl[i][2]);
                mma16816(acc[0][0], al0, bh[i][0], bh[i][2]);
                mma16816(acc[0][1], ah0, bh[i][1], bh[i][3]);
                mma16816(acc[0][1], ah0, bl[i][1], bl[i][3]);
                mma16816(acc[0][1], al0, bh[i][1], bh[i][3]);
                mma16816(acc[0][2], ah0, bh[i][4], bh[i][5]);
                mma16816(acc[0][2], ah0, bl[i][4], bl[i][5]);
                mma16816(acc[0][2], al0, bh[i][4], bh[i][5]);
                // mt = 1
                mma16816(acc[1][0], ah1, bh[i][0], bh[i][2]);
                mma16816(acc[1][0], ah1, bl[i][0], bl[i][2]);
                mma16816(acc[1][0], al1, bh[i][0], bh[i][2]);
                mma16816(acc[1][1], ah1, bh[i][1], bh[i][3]);
                mma16816(acc[1][1], ah1, bl[i][1], bl[i][3]);
                mma16816(acc[1][1], al1, bh[i][1], bh[i][3]);
                mma16816(acc[1][2], ah1, bh[i][4], bh[i][5]);
                mma16816(acc[1][2], ah1, bl[i][4], bl[i][5]);
                mma16816(acc[1][2], al1, bh[i][4], bh[i][5]);
            }
        }

        // ---- write k-partials: redF[kq4][row(batch)][col] ----
        {
            const int rbase = mg * 32 + (lane >> 2);
            #pragma unroll
            for (int mt = 0; mt < 2; ++mt) {
                #pragma unroll
                for (int nt = 0; nt < 3; ++nt) {
                    float* pr = redF + (kq4 * 64 + rbase + mt * 16) * 26
                              + nt * 8 + (lane & 3) * 2;
                    pr[0] = acc[mt][nt][0]; pr[1] = acc[mt][nt][1];
                    pr[8 * 26] = acc[mt][nt][2]; pr[8 * 26 + 1] = acc[mt][nt][3];
                }
            }
        }
        __syncthreads();

        // ---- gates (fp32): sum 4 k-partials ----
        {
            const float* r0 = redF + bb * 26;
            const float* r1 = redF + (64 + bb) * 26;
            const float* r2 = redF + (128 + bb) * 26;
            const float* r3 = redF + (192 + bb) * 26;

            const int u0 = ub;
            float ghr = r0[u0] + r1[u0] + r2[u0] + r3[u0] + bias[0][0];
            float ghz = r0[8+u0] + r1[8+u0] + r2[8+u0] + r3[8+u0] + bias[0][1];
            float ghn = r0[16+u0] + r1[16+u0] + r2[16+u0] + r3[16+u0] + bias[0][2];
            float rr = sigf(gxr[0][0] + ghr);
            float zz = sigf(gxr[0][1] + ghz);
            float nn = tanhfast(gxr[0][2] + rr * ghn);
            float hn = (1.0f - zz) * nn + zz * hp0;
            hn = mk * hn + (1.0f - mk) * hp0;
            hp0 = hn;
            outs[bb * 8 + u0] = hn;
            ohx[bb * 8 + u0]  = pack_bf16x2(hn, hn - bf16_hi(hn));

            const int u1 = ub + 4;
            ghr = r0[u1] + r1[u1] + r2[u1] + r3[u1] + bias[1][0];
            ghz = r0[8+u1] + r1[8+u1] + r2[8+u1] + r3[8+u1] + bias[1][1];
            ghn = r0[16+u1] + r1[16+u1] + r2[16+u1] + r3[16+u1] + bias[1][2];
            rr = sigf(gxr[1][0] + ghr);
            zz = sigf(gxr[1][1] + ghz);
            nn = tanhfast(gxr[1][2] + rr * ghn);
            hn = (1.0f - zz) * nn + zz * hp1;
            hn = mk * hn + (1.0f - mk) * hp1;
            hp1 = hn;
            outs[bb * 8 + u1] = hn;
            ohx[bb * 8 + u1]  = pack_bf16x2(hn, hn - bf16_hi(hn));
        }
        __syncthreads();

        // ---- coalesced stores: out + next-step hx, then arrive ----
        {
            float2 ov = *(const float2*)(outs + ob * 8 + oq * 2);
            *(float2*)(out + ((size_t)ob * LDIM + t_in) * (2 * HDIM)
                       + dir * HDIM + j0 + oq * 2) = ov;
            uint2 hv = *(const uint2*)(ohx + ob * 8 + oq * 2);
            *(uint2*)(hx + (size_t)nxt * BDIM * HDIM
                      + (size_t)ob * HDIM + j0 + oq * 2) = hv;
        }

        bar_tgt = grid_arrive(dir);
    }
}

// =====================================================================
extern "C" void kernel_launch(void* const* d_in, const int* in_sizes, int n_in,
                              void* d_out, int out_size)
{
    const float* feats      = (const float*)d_in[0];
    const float* feats_mask = (const float*)d_in[1];
    const float* w_ih_lr    = (const float*)d_in[2];
    const float* w_hh_lr    = (const float*)d_in[3];
    const float* b_ih_lr    = (const float*)d_in[4];
    const float* b_hh_lr    = (const float*)d_in[5];
    const float* w_ih_rl    = (const float*)d_in[6];
    const float* w_hh_rl    = (const float*)d_in[7];
    const float* b_ih_rl    = (const float*)d_in[8];
    const float* b_hh_rl    = (const float*)d_in[9];
    float* out = (float*)d_out;

    cudaFuncSetAttribute(scan_kernel, cudaFuncAttributeMaxDynamicSharedMemorySize,
                         SM_BYTES);

    convx_kernel<<<32768, 256>>>(feats);
    convw_kernel<<<1536, 256>>>(w_ih_lr, w_ih_rl);

    dim3 ggrid(G3 / 128, (BDIM * LDIM) / 128, 2);
    hgemm_kernel<<<ggrid, 256>>>(b_ih_lr, b_ih_rl);

    scan_kernel<<<2 * NCTA_DIR, 256, SM_BYTES>>>(
        feats_mask, w_hh_lr, b_hh_lr, w_hh_rl, b_hh_rl, out);
}